// round 1
// baseline (speedup 1.0000x reference)
#include <cuda_runtime.h>
#include <math.h>

// ---------------------------------------------------------------------------
// Problem constants
// B=8, CIN=64, COUT=64, H=W=128, R=2, HID=8, K=3, GK=15
// ---------------------------------------------------------------------------

#define BB   8
#define CIN  64
#define COUT 64
#define HH   128
#define WW   128
#define RR   2
#define HID  8
#define HW   (HH*WW)          // 16384

// ---------------------------------------------------------------------------
// Device scratch (no allocation allowed)
// ---------------------------------------------------------------------------
__device__ float g_pooled[BB*CIN*9];                 // [b][ci][yx]
__device__ float g_hid[BB*16*9];                     // [b][c(16)][yx]
// conv weights, layout [b][r][ci][kyx(9)][co]  (co fastest -> packed pairs)
__device__ float g_kern[(size_t)BB*RR*CIN*9*COUT];   // 589824 floats
__device__ float g_sa[BB*HW];
__device__ int   g_mm_min[BB];
__device__ int   g_mm_max[BB];
__device__ unsigned char g_rsel[BB*HW];

// ---------------------------------------------------------------------------
// 1) Adaptive avg pool 128x128 -> 3x3  (PyTorch bin semantics, bins overlap)
//    rows/cols bins: [0,43) [42,86) [85,128)  widths {43,44,43}
// ---------------------------------------------------------------------------
__global__ void pool_kernel(const float* __restrict__ feat) {
    const int bc = blockIdx.x;                 // b*64+ci, 0..511
    const float* src = feat + (size_t)bc * HW;
    float a[9];
    #pragma unroll
    for (int i = 0; i < 9; ++i) a[i] = 0.f;

    for (int idx = threadIdx.x; idx < HW; idx += 128) {
        float v = src[idx];
        int y = idx >> 7, x = idx & 127;
        bool rm0 = (y < 43), rm1 = (y >= 42) & (y < 86), rm2 = (y >= 85);
        bool cm0 = (x < 43), cm1 = (x >= 42) & (x < 86), cm2 = (x >= 85);
        if (rm0) { if (cm0) a[0]+=v; if (cm1) a[1]+=v; if (cm2) a[2]+=v; }
        if (rm1) { if (cm0) a[3]+=v; if (cm1) a[4]+=v; if (cm2) a[5]+=v; }
        if (rm2) { if (cm0) a[6]+=v; if (cm1) a[7]+=v; if (cm2) a[8]+=v; }
    }

    __shared__ float red[9][128];
    #pragma unroll
    for (int k = 0; k < 9; ++k) red[k][threadIdx.x] = a[k];
    __syncthreads();
    for (int s = 64; s > 0; s >>= 1) {
        if (threadIdx.x < s) {
            #pragma unroll
            for (int k = 0; k < 9; ++k)
                red[k][threadIdx.x] += red[k][threadIdx.x + s];
        }
        __syncthreads();
    }
    if (threadIdx.x < 9) {
        const float cnt[3] = {43.f, 44.f, 43.f};
        int i = threadIdx.x / 3, j = threadIdx.x % 3;
        g_pooled[bc*9 + threadIdx.x] = red[threadIdx.x][0] / (cnt[i] * cnt[j]);
    }
}

// ---------------------------------------------------------------------------
// 2) First 1x1 MLP + sigmoid: hid[b,c,yx] = sig(b1[c] + sum_ci w1[c,ci]*pooled)
// ---------------------------------------------------------------------------
__global__ void mlp1_kernel(const float* __restrict__ w1,
                            const float* __restrict__ b1) {
    const int b = blockIdx.x;
    const int t = threadIdx.x;
    if (t >= 144) return;
    const int c = t / 9, yx = t % 9;
    float v = b1[c];
    #pragma unroll 8
    for (int ci = 0; ci < CIN; ++ci)
        v += w1[c*CIN + ci] * g_pooled[(b*CIN + ci)*9 + yx];
    g_hid[(b*16 + c)*9 + yx] = 1.f / (1.f + expf(-v));
}

// ---------------------------------------------------------------------------
// 3) Kernel generation (grouped 1x1, groups=R):
//    q = r*4096 + co*64 + ci
//    kern[b,r,co,ci,yx] = b2[q] + sum_h w2[q*8+h] * hid[b, r*8+h, yx]
//    stored as g_kern[((b*2+r)*64+ci)*576 + yx*64 + co]
// ---------------------------------------------------------------------------
__global__ void kerngen_kernel(const float* __restrict__ w2,
                               const float* __restrict__ b2) {
    const int blk = blockIdx.x;               // 0..143
    const int b = blk / 18, rem = blk % 18;
    const int r = rem / 9, yx = rem % 9;

    __shared__ float hs[8];
    if (threadIdx.x < 8)
        hs[threadIdx.x] = g_hid[(b*16 + r*8 + threadIdx.x)*9 + yx];
    __syncthreads();

    for (int idx = threadIdx.x; idx < CIN*COUT; idx += 256) {
        const int co = idx & 63, ci = idx >> 6;
        const int q = r*(CIN*COUT) + co*CIN + ci;
        const float* wp = w2 + (size_t)q * HID;
        float v = b2[q];
        #pragma unroll
        for (int h = 0; h < HID; ++h) v += wp[h] * hs[h];
        g_kern[((size_t)(b*2 + r)*CIN + ci)*576 + yx*64 + co] = v;
    }
}

// ---------------------------------------------------------------------------
// 4) Guide path: sigmoid(pred) -> 15x15 gaussian conv -> per-image min/max
// ---------------------------------------------------------------------------
__global__ void initmm_kernel() {
    int t = threadIdx.x;
    if (t < BB) { g_mm_max[t] = 0; g_mm_min[t] = 0x7F7FFFFF; }
}

__global__ __launch_bounds__(256) void sa_kernel(const float* __restrict__ pred,
                                                 const float* __restrict__ gk) {
    __shared__ float sp[46][46];
    __shared__ float sg[225];
    const int b  = blockIdx.z;
    const int x0 = blockIdx.x * 32, y0 = blockIdx.y * 32;
    const int tid = threadIdx.x;

    for (int i = tid; i < 225; i += 256) sg[i] = gk[i];
    for (int i = tid; i < 46*46; i += 256) {
        int ly = i / 46, lx = i % 46;
        int gy = y0 - 7 + ly, gx = x0 - 7 + lx;
        float v = 0.f;  // conv zero-pads the sigmoid'd input
        if ((unsigned)gy < 128u && (unsigned)gx < 128u) {
            float pv = pred[b*HW + gy*128 + gx];
            v = 1.f / (1.f + expf(-pv));
        }
        sp[ly][lx] = v;
    }
    __syncthreads();

    float tmn = 3.4e38f, tmx = 0.f;   // sa >= 0 (positive * positive)
    #pragma unroll
    for (int p = 0; p < 4; ++p) {
        int id = tid + p*256;
        int py = id >> 5, px = id & 31;
        float s = 0.f;
        for (int u = 0; u < 15; ++u) {
            #pragma unroll
            for (int v = 0; v < 15; ++v)
                s += sp[py + u][px + v] * sg[u*15 + v];
        }
        g_sa[b*HW + (y0 + py)*128 + (x0 + px)] = s;
        tmn = fminf(tmn, s); tmx = fmaxf(tmx, s);
    }
    #pragma unroll
    for (int o = 16; o; o >>= 1) {
        tmn = fminf(tmn, __shfl_xor_sync(0xffffffffu, tmn, o));
        tmx = fmaxf(tmx, __shfl_xor_sync(0xffffffffu, tmx, o));
    }
    __shared__ float rmn[8], rmx[8];
    if ((tid & 31) == 0) { rmn[tid >> 5] = tmn; rmx[tid >> 5] = tmx; }
    __syncthreads();
    if (tid == 0) {
        #pragma unroll
        for (int w = 0; w < 8; ++w) { tmn = fminf(tmn, rmn[w]); tmx = fmaxf(tmx, rmx[w]); }
        // positive floats: int compare == float compare
        atomicMin(&g_mm_min[b], __float_as_int(tmn));
        atomicMax(&g_mm_max[b], __float_as_int(tmx));
    }
}

// h = max(minmaxnorm(sa), sigmoid(pred)); argmax([h,1-h]) -> r = (h<0.5) ? 1 : 0
__global__ void rsel_kernel(const float* __restrict__ pred) {
    int gid = blockIdx.x * 256 + threadIdx.x;
    if (gid >= BB*HW) return;
    int b = gid >> 14;
    float mn = __int_as_float(g_mm_min[b]);
    float mx = __int_as_float(g_mm_max[b]);
    float sa = (g_sa[gid] - mn) / (mx - mn + 1e-8f);
    float p  = 1.f / (1.f + expf(-pred[gid]));
    float h  = fmaxf(sa, p);
    g_rsel[gid] = (h < 0.5f) ? 1 : 0;
}

// ---------------------------------------------------------------------------
// 5) Main dynamic conv with per-pixel r selection.
//    Block: one batch, 32x8 pixel tile, all 64 couts.
//    Thread: 1 pixel, 64 couts as 32 packed f32x2 accumulators.
//    Weights staged in smem for BOTH r (per-warp broadcast reads).
//    Packed fma.rn.f32x2 => 2x fp32 FMA throughput, exact fp32 math.
// ---------------------------------------------------------------------------
#define CTX 32
#define CTY 8

__global__ __launch_bounds__(256, 2)
void conv_main_kernel(const float* __restrict__ feat, float* __restrict__ out) {
    __shared__ float s_feat[8][CTY + 2][CTX + 2];                // [8][10][34]
    __shared__ __align__(16) float s_w[2][8][9][64];             // 36864 B

    const int tx = threadIdx.x, ty = threadIdx.y;
    const int tid = ty * CTX + tx;
    const int b  = blockIdx.z;
    const int x0 = blockIdx.x * CTX;
    const int y0 = blockIdx.y * CTY;
    const int y = y0 + ty, x = x0 + tx;
    const int r = g_rsel[b*HW + y*128 + x];

    unsigned long long acc[32];
    #pragma unroll
    for (int i = 0; i < 32; ++i) acc[i] = 0ull;

    const unsigned sw_base =
        (unsigned)__cvta_generic_to_shared(&s_w[0][0][0][0]) + (unsigned)r * (8*9*64*4);

    for (int cc = 0; cc < 8; ++cc) {
        __syncthreads();   // protect smem reuse from previous chunk
        // --- stage feat chunk (8 ci) with halo + zero padding ---
        const float* fsrc = feat + ((size_t)(b*CIN + cc*8)) * HW;
        for (int i = tid; i < 8*10*34; i += 256) {
            int ci = i / 340, rem = i % 340;
            int ly = rem / 34, lx = rem % 34;
            int gy = y0 - 1 + ly, gx = x0 - 1 + lx;
            float v = 0.f;
            if ((unsigned)gy < 128u && (unsigned)gx < 128u)
                v = fsrc[ci*HW + gy*128 + gx];
            s_feat[ci][ly][lx] = v;
        }
        // --- stage weight chunk for both r (contiguous slabs, float4) ---
        {
            const float4* w0 = (const float4*)(g_kern + ((size_t)(b*2 + 0)*CIN + cc*8)*576);
            const float4* w1 = (const float4*)(g_kern + ((size_t)(b*2 + 1)*CIN + cc*8)*576);
            float4* sd = (float4*)s_w;
            for (int i = tid; i < 1152; i += 256) sd[i]        = w0[i];
            for (int i = tid; i < 1152; i += 256) sd[1152 + i] = w1[i];
        }
        __syncthreads();

        // --- compute: 8 ci x 9 taps x 64 couts (packed pairs) ---
        for (int ci = 0; ci < 8; ++ci) {
            #pragma unroll
            for (int k = 0; k < 9; ++k) {
                const int ky = k / 3, kx = k % 3;
                float f = s_feat[ci][ty + ky][tx + kx];
                unsigned long long fp;
                asm("mov.b64 %0, {%1, %1};" : "=l"(fp) : "f"(f));
                const unsigned wa = sw_base + (unsigned)(ci*9 + k) * 256;
                #pragma unroll
                for (int q = 0; q < 16; ++q) {
                    unsigned long long wlo, whi;
                    asm volatile("ld.shared.v2.b64 {%0, %1}, [%2];"
                                 : "=l"(wlo), "=l"(whi) : "r"(wa + q*16));
                    asm("fma.rn.f32x2 %0, %1, %2, %0;" : "+l"(acc[2*q])   : "l"(fp), "l"(wlo));
                    asm("fma.rn.f32x2 %0, %1, %2, %0;" : "+l"(acc[2*q+1]) : "l"(fp), "l"(whi));
                }
            }
        }
    }

    // --- epilogue: unpack and write (coalesced per co across warp) ---
    float* op = out + (size_t)b*COUT*HW + y*128 + x;
    #pragma unroll
    for (int j = 0; j < 32; ++j) {
        float lo, hi;
        asm("mov.b64 {%0, %1}, %2;" : "=f"(lo), "=f"(hi) : "l"(acc[j]));
        op[(size_t)(2*j)   * HW] = lo;
        op[(size_t)(2*j+1) * HW] = hi;
    }
}

// ---------------------------------------------------------------------------
// Launch: inputs in metadata order: feat, pred, w1, b1, w2, b2, gk
// ---------------------------------------------------------------------------
extern "C" void kernel_launch(void* const* d_in, const int* in_sizes, int n_in,
                              void* d_out, int out_size) {
    const float* feat = (const float*)d_in[0];
    const float* pred = (const float*)d_in[1];
    const float* w1   = (const float*)d_in[2];
    const float* b1   = (const float*)d_in[3];
    const float* w2   = (const float*)d_in[4];
    const float* b2   = (const float*)d_in[5];
    const float* gk   = (const float*)d_in[6];
    float* out = (float*)d_out;

    pool_kernel<<<BB*CIN, 128>>>(feat);
    mlp1_kernel<<<BB, 160>>>(w1, b1);
    kerngen_kernel<<<BB*RR*9, 256>>>(w2, b2);

    initmm_kernel<<<1, 32>>>();
    dim3 gsa(4, 4, BB);
    sa_kernel<<<gsa, 256>>>(pred, gk);
    rsel_kernel<<<(BB*HW + 255)/256, 256>>>(pred);

    dim3 gc(WW/CTX, HH/CTY, BB);
    dim3 bc(CTX, CTY);
    conv_main_kernel<<<gc, bc>>>(feat, out);
}